// round 2
// baseline (speedup 1.0000x reference)
#include <cuda_runtime.h>
#include <math.h>

// Problem constants
#define N_TOK 16384
#define MD    2048     // model dim (K of big GEMM)
#define PD    256      // proj dim
#define NE    64       // experts
#define TM    64       // tokens per block
#define TK    16       // K tile
#define NTHREADS 256
#define CLAMP_MAX_F 4.6051701859880913680f  // log(100)

// Device-global scratch (no allocation allowed)
__device__ float g_simN[PD * NE];   // column-normalized sim, [p][e]
__device__ float g_scale;
__device__ int   g_active;

// ---------------------------------------------------------------------------
// Prep: normalize sim_matrix columns (dim=0), compute logit scale + active cnt
// ---------------------------------------------------------------------------
__global__ void prep_kernel(const float* __restrict__ sim,
                            const float* __restrict__ temp,
                            const float* __restrict__ mask) {
    int e = threadIdx.x;
    if (e < NE) {
        float s = 0.f;
        #pragma unroll 4
        for (int p = 0; p < PD; ++p) {
            float v = sim[p * NE + e];
            s = fmaf(v, v, s);
        }
        float inv = 1.0f / fmaxf(sqrtf(s), 1e-12f);
        #pragma unroll 4
        for (int p = 0; p < PD; ++p)
            g_simN[p * NE + e] = sim[p * NE + e] * inv;
    }
    if (threadIdx.x == 0) {
        g_scale = expf(fminf(temp[0], CLAMP_MAX_F));
        float a = 0.f;
        for (int i = 0; i < NE; ++i) a += mask[i];
        g_active = (int)a;
    }
}

// ---------------------------------------------------------------------------
// Fused gate kernel: GEMM1 -> row L2-norm -> GEMM2 -> scale/mask -> logits out
//                    -> softmax -> pairwise top-k count -> top_k out
//
// Shared memory layout (floats):
//   [0,        16384)  simN_s   [PD][NE]      (persistent, 64 KB)
//   [16384,    32768)  union:
//        GEMM phase: As [TK][TM] (1024) ++ Bs [TK][PD] (4096)
//        Post phase: Hs [TM][PD]          (64 KB)
//   [32768,    33280)  sc [8 warps][NE]       (2 KB)
// Total: 33280 floats = 133120 bytes dynamic smem.
// ---------------------------------------------------------------------------
__global__ void __launch_bounds__(NTHREADS, 1)
gate_kernel(const float* __restrict__ x,
            const float* __restrict__ W,
            const float* __restrict__ bias,
            const float* __restrict__ mask,
            float* __restrict__ out_logits,
            float* __restrict__ out_topk) {
    extern __shared__ float smem[];
    float* simN_s = smem;                       // [PD][NE]
    float* As     = smem + PD * NE;             // [TK][TM]
    float* Bs     = As + TK * TM;               // [TK][PD]
    float* Hs     = smem + PD * NE;             // [TM][PD]  (union w/ As,Bs)
    float* scbuf  = smem + PD * NE + TM * PD;   // [8][NE]

    const int tid  = threadIdx.x;
    const int w    = tid >> 5;      // warp 0..7, owns tokens w*8 .. w*8+7
    const int lane = tid & 31;
    const int row0 = blockIdx.x * TM;

    // Stage simN into smem (overlaps with GEMM prologue loads)
    for (int i = tid; i < PD * NE; i += NTHREADS)
        simN_s[i] = g_simN[i];

    // ------------------- GEMM1: h[TM][PD] = x_tile @ W^T -------------------
    float acc[8][8];
    #pragma unroll
    for (int i = 0; i < 8; ++i)
        #pragma unroll
        for (int j = 0; j < 8; ++j) acc[i][j] = 0.f;

    const int r = tid >> 2;   // 0..63 : token row (for X) / proj row group (for W)
    const int q = tid & 3;    // 0..3  : k-quad
    const float* xg = x + (size_t)(row0 + r) * MD + q * 4;

    float4 xa;
    float4 wb[4];
    // prologue: stage k-tile 0
    xa = *(const float4*)(xg);
    #pragma unroll
    for (int it = 0; it < 4; ++it)
        wb[it] = *(const float4*)(W + (size_t)(r + it * 64) * MD + q * 4);

    const int NKT = MD / TK;  // 128
    for (int kt = 0; kt < NKT; ++kt) {
        // commit staged tile to smem (transposed: [k][m] / [k][p])
        #pragma unroll
        for (int u = 0; u < 4; ++u)
            As[(q * 4 + u) * TM + r] = ((const float*)&xa)[u];
        #pragma unroll
        for (int it = 0; it < 4; ++it)
            #pragma unroll
            for (int u = 0; u < 4; ++u)
                Bs[(q * 4 + u) * PD + (r + it * 64)] = ((const float*)&wb[it])[u];
        __syncthreads();

        // prefetch next k-tile (latency hidden under compute)
        if (kt + 1 < NKT) {
            int k0 = (kt + 1) * TK;
            xa = *(const float4*)(xg + k0);
            #pragma unroll
            for (int it = 0; it < 4; ++it)
                wb[it] = *(const float4*)(W + (size_t)(r + it * 64) * MD + k0 + q * 4);
        }

        // compute: 16 k-steps, 8x8 micro-tile
        #pragma unroll
        for (int k = 0; k < TK; ++k) {
            float a[8], b[8];
            // a-frag: 8 contiguous tokens of this warp (broadcast across lanes)
            float4 a0 = *(const float4*)(As + k * TM + w * 8);
            float4 a1 = *(const float4*)(As + k * TM + w * 8 + 4);
            a[0] = a0.x; a[1] = a0.y; a[2] = a0.z; a[3] = a0.w;
            a[4] = a1.x; a[5] = a1.y; a[6] = a1.z; a[7] = a1.w;
            // b-frag: strided proj columns p = lane + 32*j (conflict-free)
            #pragma unroll
            for (int j = 0; j < 8; ++j) b[j] = Bs[k * PD + lane + 32 * j];
            #pragma unroll
            for (int i = 0; i < 8; ++i)
                #pragma unroll
                for (int j = 0; j < 8; ++j)
                    acc[i][j] = fmaf(a[i], b[j], acc[i][j]);
        }
        __syncthreads();
    }

    // bias add
    float bj[8];
    #pragma unroll
    for (int j = 0; j < 8; ++j) bj[j] = __ldg(bias + lane + 32 * j);
    #pragma unroll
    for (int i = 0; i < 8; ++i)
        #pragma unroll
        for (int j = 0; j < 8; ++j) acc[i][j] += bj[j];

    // ------------- row L2 normalize (intra-warp) + stage to Hs -------------
    // (Hs overlaps As/Bs; final __syncthreads of GEMM loop makes that safe.
    //  Each warp only reads back its own rows -> __syncwarp is enough.)
    #pragma unroll
    for (int i = 0; i < 8; ++i) {
        float s = 0.f;
        #pragma unroll
        for (int j = 0; j < 8; ++j) s = fmaf(acc[i][j], acc[i][j], s);
        #pragma unroll
        for (int o = 16; o > 0; o >>= 1) s += __shfl_xor_sync(0xffffffffu, s, o);
        float inv = 1.0f / fmaxf(sqrtf(s), 1e-12f);
        #pragma unroll
        for (int j = 0; j < 8; ++j)
            Hs[(w * 8 + i) * PD + lane + 32 * j] = acc[i][j] * inv;
    }
    __syncwarp();

    // ---------------- GEMM2: logits[8][64] = hn @ simN ---------------------
    const float scale  = g_scale;
    const int   active = g_active;
    const float* Hw = Hs + (w * 8) * PD;

    float lg0[8], lg1[8];
    #pragma unroll
    for (int i = 0; i < 8; ++i) { lg0[i] = 0.f; lg1[i] = 0.f; }

    for (int p = 0; p < PD; p += 4) {
        float s0[4], s1[4];
        #pragma unroll
        for (int u = 0; u < 4; ++u) {
            s0[u] = simN_s[(p + u) * NE + lane];
            s1[u] = simN_s[(p + u) * NE + lane + 32];
        }
        #pragma unroll
        for (int i = 0; i < 8; ++i) {
            float4 h4 = *(const float4*)(Hw + i * PD + p);
            lg0[i] = fmaf(h4.x, s0[0], lg0[i]);
            lg1[i] = fmaf(h4.x, s1[0], lg1[i]);
            lg0[i] = fmaf(h4.y, s0[1], lg0[i]);
            lg1[i] = fmaf(h4.y, s1[1], lg1[i]);
            lg0[i] = fmaf(h4.z, s0[2], lg0[i]);
            lg1[i] = fmaf(h4.z, s1[2], lg1[i]);
            lg0[i] = fmaf(h4.w, s0[3], lg0[i]);
            lg1[i] = fmaf(h4.w, s1[3], lg1[i]);
        }
    }

    // ------------- scale, mask, write logits; softmax; top-k ---------------
    const float m0 = __ldg(mask + lane);
    const float m1 = __ldg(mask + lane + 32);
    float* scw = scbuf + w * NE;

    #pragma unroll 1
    for (int i = 0; i < 8; ++i) {
        const int t = row0 + w * 8 + i;
        float v0 = (m0 == 0.f) ? -1e9f : lg0[i] * scale;
        float v1 = (m1 == 0.f) ? -1e9f : lg1[i] * scale;
        out_logits[(size_t)t * NE + lane]      = v0;
        out_logits[(size_t)t * NE + lane + 32] = v1;

        // softmax over 64 within the warp
        float mx = fmaxf(v0, v1);
        #pragma unroll
        for (int o = 16; o > 0; o >>= 1)
            mx = fmaxf(mx, __shfl_xor_sync(0xffffffffu, mx, o));
        float e0 = expf(v0 - mx), e1 = expf(v1 - mx);
        float sm = e0 + e1;
        #pragma unroll
        for (int o = 16; o > 0; o >>= 1)
            sm += __shfl_xor_sync(0xffffffffu, sm, o);
        float inv = 1.0f / sm;
        float sc0 = fmaf(e0, inv, 1e-14f);
        float sc1 = fmaf(e1, inv, 1e-14f);

        // pairwise prefix-of-larger sum; keep iff (strictly-preceding sum) < 1
        scw[lane]      = sc0;
        scw[lane + 32] = sc1;
        __syncwarp();
        float pre0 = 0.f, pre1 = 0.f;
        #pragma unroll
        for (int e = 0; e < NE; ++e) {
            float s = scw[e];
            bool g0 = (s > sc0) || (s == sc0 && e < lane);
            bool g1 = (s > sc1) || (s == sc1 && e < lane + 32);
            pre0 += g0 ? s : 0.f;
            pre1 += g1 ? s : 0.f;
        }
        int cnt = (pre0 < 1.0f ? 1 : 0) + (pre1 < 1.0f ? 1 : 0);
        #pragma unroll
        for (int o = 16; o > 0; o >>= 1)
            cnt += __shfl_xor_sync(0xffffffffu, cnt, o);
        if (lane == 0 && out_topk != nullptr)
            out_topk[t] = (float)min(cnt, active);
        __syncwarp();  // protect scw before next token reuses it
    }
}

// ---------------------------------------------------------------------------
extern "C" void kernel_launch(void* const* d_in, const int* in_sizes, int n_in,
                              void* d_out, int out_size) {
    const float* x    = (const float*)d_in[0];  // [16384, 2048]
    const float* W    = (const float*)d_in[1];  // [256, 2048]
    const float* b    = (const float*)d_in[2];  // [256]
    const float* sim  = (const float*)d_in[3];  // [256, 64]
    const float* temp = (const float*)d_in[4];  // [1]
    const float* mask = (const float*)d_in[5];  // [64]

    float* out = (float*)d_out;
    // Output packing: logits [N,64] f32 first, then top_k (as float) [N].
    float* out_topk = (out_size >= N_TOK * NE + N_TOK) ? (out + (size_t)N_TOK * NE)
                                                       : nullptr;

    prep_kernel<<<1, 64>>>(sim, temp, mask);

    const int smem_bytes = (PD * NE + TM * PD + 8 * NE) * (int)sizeof(float); // 133120
    cudaFuncSetAttribute(gate_kernel,
                         cudaFuncAttributeMaxDynamicSharedMemorySize, smem_bytes);
    gate_kernel<<<N_TOK / TM, NTHREADS, smem_bytes>>>(x, W, b, mask, out, out_topk);
}

// round 4
// speedup vs baseline: 2.4209x; 2.4209x over previous
#include <cuda_runtime.h>
#include <cuda_bf16.h>
#include <math.h>
#include <stdint.h>

#define N_TOK 16384
#define MD    2048
#define PD    256
#define NE    64
#define TM    128
#define KC    32          // k elements per chunk
#define NCH   64
#define NTHREADS 256
#define CLAMP_MAX_F 4.6051701859880913680f
#define ASTR  40          // smem row stride in halves (80B) -> conflict-free ldmatrix
#define HSTR  264         // Hs row stride in floats

// ---- device-global scratch (no allocation allowed) ----
__device__ __nv_bfloat16 g_Whi[PD * MD];
__device__ __nv_bfloat16 g_Wlo[PD * MD];
__device__ float g_simN[PD * NE];
__device__ float g_scale;
__device__ int   g_active;

// ---- smem layout (bytes) ----
// mainloop: two stage buffers of 61440 B at 0 and 61440.
//   within a stage: A_hi 0 (128*80=10240), A_lo 10240, B_hi 20480 (256*80=20480), B_lo 40960
// epilogue (after mainloop, overlays stages): Hs [128][264] f32 @0 (135168)
// non-overlapping (preloadable): part@135168(2048) inv@137216(512) scw@137728(2048)
//   sim@139776(65536) bias@205312(1024) mask@206336(256)
#define STG(s)  ((s) * 61440)
#define A_HI_O  0
#define A_LO_O  10240
#define B_HI_O  20480
#define B_LO_O  40960
#define OF_HS   0
#define OF_PART 135168
#define OF_INV  137216
#define OF_SCW  137728
#define OF_SIM  139776
#define OF_BIAS 205312
#define OF_MASK 206336
#define SMEM_BYTES 206592

__device__ __forceinline__ uint32_t smem_u32(const void* p) {
    uint32_t a;
    asm("{ .reg .u64 t; cvta.to.shared.u64 t, %1; cvt.u32.u64 %0, t; }" : "=r"(a) : "l"(p));
    return a;
}
__device__ __forceinline__ uint32_t pack2(__nv_bfloat16 a, __nv_bfloat16 b) {
    __nv_bfloat162 t; t.x = a; t.y = b;
    return *reinterpret_cast<uint32_t*>(&t);
}
#define CP16(dst, src) asm volatile("cp.async.cg.shared.global [%0], [%1], 16;" \
    :: "r"(dst), "l"(src) : "memory")
#define CP_COMMIT() asm volatile("cp.async.commit_group;" ::: "memory")
#define CP_WAIT0()  asm volatile("cp.async.wait_group 0;" ::: "memory")
#define LDSM4(r, a) asm volatile("ldmatrix.sync.aligned.m8n8.x4.shared.b16 {%0,%1,%2,%3}, [%4];" \
    : "=r"((r)[0]), "=r"((r)[1]), "=r"((r)[2]), "=r"((r)[3]) : "r"(a))
#define LDSM2(r, a) asm volatile("ldmatrix.sync.aligned.m8n8.x2.shared.b16 {%0,%1}, [%2];" \
    : "=r"((r)[0]), "=r"((r)[1]) : "r"(a))
#define MMA(d, a, b) asm volatile( \
    "mma.sync.aligned.m16n8k16.row.col.f32.bf16.bf16.f32 " \
    "{%0,%1,%2,%3},{%4,%5,%6,%7},{%8,%9},{%0,%1,%2,%3};" \
    : "+f"((d)[0]), "+f"((d)[1]), "+f"((d)[2]), "+f"((d)[3]) \
    : "r"((a)[0]), "r"((a)[1]), "r"((a)[2]), "r"((a)[3]), "r"((b)[0]), "r"((b)[1]))

// ---------------------------------------------------------------------------
// Prep kernels
// ---------------------------------------------------------------------------
__global__ void prep_w(const float* __restrict__ W) {
    int i = (blockIdx.x * blockDim.x + threadIdx.x) * 16;
    #pragma unroll
    for (int k = 0; k < 16; ++k) {
        float v = W[i + k];
        __nv_bfloat16 h = __float2bfloat16(v);
        g_Whi[i + k] = h;
        g_Wlo[i + k] = __float2bfloat16(v - __bfloat162float(h));
    }
}

__global__ void prep_sim(const float* __restrict__ sim,
                         const float* __restrict__ temp,
                         const float* __restrict__ mask) {
    int e = threadIdx.x;
    if (e < NE) {
        float s = 0.f;
        #pragma unroll 4
        for (int p = 0; p < PD; ++p) { float v = sim[p * NE + e]; s = fmaf(v, v, s); }
        float inv = 1.0f / fmaxf(sqrtf(s), 1e-12f);
        #pragma unroll 4
        for (int p = 0; p < PD; ++p) g_simN[p * NE + e] = sim[p * NE + e] * inv;
    }
    if (threadIdx.x == 0) {
        g_scale = expf(fminf(temp[0], CLAMP_MAX_F));
        float a = 0.f;
        for (int i = 0; i < NE; ++i) a += mask[i];
        g_active = (int)a;
    }
}

// ---------------------------------------------------------------------------
// Main fused kernel
// ---------------------------------------------------------------------------
__device__ __forceinline__ void issue_w(uint32_t smb, int s, int c, int tid) {
    #pragma unroll
    for (int u = 0; u < 4; ++u) {
        int i = u * NTHREADS + tid;
        int n = i >> 2, seg = i & 3;
        uint32_t dh = smb + STG(s) + B_HI_O + n * 80 + seg * 16;
        uint32_t dl = smb + STG(s) + B_LO_O + n * 80 + seg * 16;
        CP16(dh, (const void*)(g_Whi + (size_t)n * MD + c * KC + seg * 8));
        CP16(dl, (const void*)(g_Wlo + (size_t)n * MD + c * KC + seg * 8));
    }
}

__device__ __forceinline__ void store_x(char* sm, int s, int xr, int xh,
                                        const float4* v) {
    uint32_t hi[8], lo[8];
    #pragma unroll
    for (int u = 0; u < 4; ++u) {
        const float* f = (const float*)&v[u];
        #pragma unroll
        for (int j = 0; j < 2; ++j) {
            float a0 = f[j * 2], a1 = f[j * 2 + 1];
            __nv_bfloat16 h0 = __float2bfloat16(a0), h1 = __float2bfloat16(a1);
            float l0 = a0 - __bfloat162float(h0), l1 = a1 - __bfloat162float(h1);
            hi[u * 2 + j] = pack2(h0, h1);
            lo[u * 2 + j] = pack2(__float2bfloat16(l0), __float2bfloat16(l1));
        }
    }
    char* bh = sm + STG(s) + A_HI_O + xr * 80 + xh * 32;
    char* bl = sm + STG(s) + A_LO_O + xr * 80 + xh * 32;
    *(uint4*)bh        = *(uint4*)(hi);
    *(uint4*)(bh + 16) = *(uint4*)(hi + 4);
    *(uint4*)bl        = *(uint4*)(lo);
    *(uint4*)(bl + 16) = *(uint4*)(lo + 4);
}

__global__ void __launch_bounds__(NTHREADS, 1)
gate_kernel(const float* __restrict__ x,
            const float* __restrict__ bias,
            const float* __restrict__ mask,
            float* __restrict__ out_logits,
            float* __restrict__ out_topk) {
    extern __shared__ char sm[];
    const uint32_t smb = smem_u32(sm);
    const int tid = threadIdx.x, wid = tid >> 5, lane = tid & 31;
    const int mh = wid >> 2, nq = wid & 3;
    const int row0 = blockIdx.x * TM;

    // preload sim / bias / mask (regions do not overlap stage buffers)
    {
        float* simS = (float*)(sm + OF_SIM);
        for (int i = tid; i < PD * NE; i += NTHREADS) simS[i] = g_simN[i];
        ((float*)(sm + OF_BIAS))[tid] = bias[tid];
        if (tid < NE) ((float*)(sm + OF_MASK))[tid] = mask[tid];
    }

    const int xr = tid >> 1, xh = tid & 1;
    const float* gx = x + (size_t)(row0 + xr) * MD + xh * 16;

    float acc[4][8][4];
    #pragma unroll
    for (int mi = 0; mi < 4; ++mi)
        #pragma unroll
        for (int ni = 0; ni < 8; ++ni)
            #pragma unroll
            for (int u = 0; u < 4; ++u) acc[mi][ni][u] = 0.f;

    // prologue: fill buffer 0
    float4 xa[4];
    issue_w(smb, 0, 0, tid);
    CP_COMMIT();
    #pragma unroll
    for (int u = 0; u < 4; ++u) xa[u] = *(const float4*)(gx + u * 4);
    store_x(sm, 0, xr, xh, xa);
    CP_WAIT0();
    __syncthreads();

    for (int c = 0; c < NCH; ++c) {
        const int s = c & 1;
        if (c + 1 < NCH) {
            issue_w(smb, s ^ 1, c + 1, tid);
            CP_COMMIT();
            const float* gxc = gx + (c + 1) * KC;
            #pragma unroll
            for (int u = 0; u < 4; ++u) xa[u] = *(const float4*)(gxc + u * 4);
        }
        // compute this chunk: 2 k16 steps, 3 split terms
        #pragma unroll
        for (int ks = 0; ks < 2; ++ks) {
            uint32_t ah[4][4], al[4][4];
            #pragma unroll
            for (int mi = 0; mi < 4; ++mi) {
                uint32_t ar = smb + STG(s) + A_HI_O
                            + (mh * 64 + mi * 16 + (lane & 15)) * 80
                            + ((lane >> 4) * 8 + ks * 16) * 2;
                LDSM4(ah[mi], ar);
                LDSM4(al[mi], ar + (A_LO_O - A_HI_O));
            }
            uint32_t bh[8][2], bl[8][2];
            const int ln = lane & 15;
            #pragma unroll
            for (int ni = 0; ni < 8; ++ni) {
                uint32_t br = smb + STG(s) + B_HI_O
                            + (nq * 64 + ni * 8 + (ln & 7)) * 80
                            + (ks * 16 + ((ln >> 3) & 1) * 8) * 2;
                LDSM2(bh[ni], br);
                LDSM2(bl[ni], br + (B_LO_O - B_HI_O));
            }
            #pragma unroll
            for (int mi = 0; mi < 4; ++mi)
                #pragma unroll
                for (int ni = 0; ni < 8; ++ni) {
                    MMA(acc[mi][ni], ah[mi], bh[ni]);
                    MMA(acc[mi][ni], ah[mi], bl[ni]);
                    MMA(acc[mi][ni], al[mi], bh[ni]);
                }
        }
        if (c + 1 < NCH) {
            store_x(sm, s ^ 1, xr, xh, xa);
            CP_WAIT0();
        }
        __syncthreads();
    }

    // ---------------- epilogue: bias + row L2 norm ----------------
    float* partS = (float*)(sm + OF_PART);
    const float* biasS = (const float*)(sm + OF_BIAS);
    #pragma unroll
    for (int mi = 0; mi < 4; ++mi) {
        float pl = 0.f, ph = 0.f;
        #pragma unroll
        for (int ni = 0; ni < 8; ++ni) {
            const int c0 = nq * 64 + ni * 8 + (lane & 3) * 2;
            float b0 = biasS[c0], b1 = biasS[c0 + 1];
            float* d = acc[mi][ni];
            d[0] += b0; d[1] += b1; d[2] += b0; d[3] += b1;
            pl = fmaf(d[0], d[0], fmaf(d[1], d[1], pl));
            ph = fmaf(d[2], d[2], fmaf(d[3], d[3], ph));
        }
        pl += __shfl_xor_sync(0xffffffffu, pl, 1);
        pl += __shfl_xor_sync(0xffffffffu, pl, 2);
        ph += __shfl_xor_sync(0xffffffffu, ph, 1);
        ph += __shfl_xor_sync(0xffffffffu, ph, 2);
        if ((lane & 3) == 0) {
            int r = mh * 64 + mi * 16 + (lane >> 2);
            partS[nq * 128 + r]     = pl;
            partS[nq * 128 + r + 8] = ph;
        }
    }
    __syncthreads();
    if (tid < 128) {
        float s = partS[tid] + partS[128 + tid] + partS[256 + tid] + partS[384 + tid];
        ((float*)(sm + OF_INV))[tid] = 1.0f / fmaxf(sqrtf(s), 1e-12f);
    }
    __syncthreads();

    // write hn to Hs (overlays dead stage buffers)
    float* Hs = (float*)(sm + OF_HS);
    const float* invS = (const float*)(sm + OF_INV);
    #pragma unroll
    for (int mi = 0; mi < 4; ++mi) {
        const int rl = mh * 64 + mi * 16 + (lane >> 2), rh = rl + 8;
        const float il = invS[rl], ih = invS[rh];
        #pragma unroll
        for (int ni = 0; ni < 8; ++ni) {
            const int c0 = nq * 64 + ni * 8 + (lane & 3) * 2;
            const float* d = acc[mi][ni];
            *(float2*)&Hs[rl * HSTR + c0] = make_float2(d[0] * il, d[1] * il);
            *(float2*)&Hs[rh * HSTR + c0] = make_float2(d[2] * ih, d[3] * ih);
        }
    }
    __syncthreads();

    // ---------------- GEMM2 (fp32 SIMT): warp owns 16 tokens ----------------
    const float scale = g_scale;
    const int active = g_active;
    const float* simS = (const float*)(sm + OF_SIM);
    const float* Hw = Hs + (size_t)(wid * 16) * HSTR;

    float lg0[16], lg1[16];
    #pragma unroll
    for (int i = 0; i < 16; ++i) { lg0[i] = 0.f; lg1[i] = 0.f; }

    for (int p = 0; p < PD; p += 4) {
        float s0[4], s1[4];
        #pragma unroll
        for (int u = 0; u < 4; ++u) {
            s0[u] = simS[(p + u) * NE + lane];
            s1[u] = simS[(p + u) * NE + lane + 32];
        }
        #pragma unroll
        for (int i = 0; i < 16; ++i) {
            float4 h4 = *(const float4*)(Hw + i * HSTR + p);
            lg0[i] = fmaf(h4.x, s0[0], lg0[i]);
            lg1[i] = fmaf(h4.x, s1[0], lg1[i]);
            lg0[i] = fmaf(h4.y, s0[1], lg0[i]);
            lg1[i] = fmaf(h4.y, s1[1], lg1[i]);
            lg0[i] = fmaf(h4.z, s0[2], lg0[i]);
            lg1[i] = fmaf(h4.z, s1[2], lg1[i]);
            lg0[i] = fmaf(h4.w, s0[3], lg0[i]);
            lg1[i] = fmaf(h4.w, s1[3], lg1[i]);
        }
    }

    // --------- scale, mask, logits store, softmax, top-k (round-1 proven) ---------
    const float* mk = (const float*)(sm + OF_MASK);
    const float m0 = mk[lane];
    const float m1 = mk[lane + 32];
    float* scw = (float*)(sm + OF_SCW) + wid * NE;

    #pragma unroll 1
    for (int i = 0; i < 16; ++i) {
        const int t = row0 + wid * 16 + i;
        float v0 = (m0 == 0.f) ? -1e9f : lg0[i] * scale;
        float v1 = (m1 == 0.f) ? -1e9f : lg1[i] * scale;
        out_logits[(size_t)t * NE + lane]      = v0;
        out_logits[(size_t)t * NE + lane + 32] = v1;

        float mx = fmaxf(v0, v1);
        #pragma unroll
        for (int o = 16; o > 0; o >>= 1)
            mx = fmaxf(mx, __shfl_xor_sync(0xffffffffu, mx, o));
        float e0 = expf(v0 - mx), e1 = expf(v1 - mx);
        float smv = e0 + e1;
        #pragma unroll
        for (int o = 16; o > 0; o >>= 1)
            smv += __shfl_xor_sync(0xffffffffu, smv, o);
        float inv = 1.0f / smv;
        float sc0 = fmaf(e0, inv, 1e-14f);
        float sc1 = fmaf(e1, inv, 1e-14f);

        scw[lane] = sc0; scw[lane + 32] = sc1;
        __syncwarp();
        float pre0 = 0.f, pre1 = 0.f;
        #pragma unroll
        for (int e = 0; e < NE; ++e) {
            float s = scw[e];
            bool g0 = (s > sc0) || (s == sc0 && e < lane);
            bool g1 = (s > sc1) || (s == sc1 && e < lane + 32);
            pre0 += g0 ? s : 0.f;
            pre1 += g1 ? s : 0.f;
        }
        int cnt = (pre0 < 1.0f ? 1 : 0) + (pre1 < 1.0f ? 1 : 0);
        #pragma unroll
        for (int o = 16; o > 0; o >>= 1)
            cnt += __shfl_xor_sync(0xffffffffu, cnt, o);
        if (lane == 0 && out_topk != nullptr)
            out_topk[t] = (float)min(cnt, active);
        __syncwarp();
    }
}

// ---------------------------------------------------------------------------
extern "C" void kernel_launch(void* const* d_in, const int* in_sizes, int n_in,
                              void* d_out, int out_size) {
    const float* x    = (const float*)d_in[0];
    const float* W    = (const float*)d_in[1];
    const float* b    = (const float*)d_in[2];
    const float* sim  = (const float*)d_in[3];
    const float* temp = (const float*)d_in[4];
    const float* mask = (const float*)d_in[5];

    float* out = (float*)d_out;
    float* out_topk = (out_size >= N_TOK * NE + N_TOK) ? (out + (size_t)N_TOK * NE)
                                                       : nullptr;

    prep_w<<<128, 256>>>(W);
    prep_sim<<<1, 64>>>(sim, temp, mask);

    cudaFuncSetAttribute(gate_kernel,
                         cudaFuncAttributeMaxDynamicSharedMemorySize, SMEM_BYTES);
    gate_kernel<<<N_TOK / TM, NTHREADS, SMEM_BYTES>>>(x, b, mask, out, out_topk);
}